// round 3
// baseline (speedup 1.0000x reference)
#include <cuda_runtime.h>

#define ITEMS 32
#define BLOCK 256
#define CHUNK (ITEMS * BLOCK)   // 8192 samples per block
#define MAXBLKS 65536

// Scratch (no allocation allowed)
__device__ float2 g_agg[MAXBLKS];     // per-block zero-state end state (aggregate)
__device__ int    g_status[MAXBLKS];  // 0 = not ready, 1 = aggregate published

// Affine map s' = M s + v, M lower-triangular [[m00,0],[m10,m11]]
struct Aff { float m00, m10, m11, v0, v1; };

__device__ __forceinline__ Aff aff_combine(const Aff& B, const Aff& A) {
    Aff r;
    r.m00 = B.m00 * A.m00;
    r.m10 = fmaf(B.m10, A.m00, B.m11 * A.m10);
    r.m11 = B.m11 * A.m11;
    r.v0  = fmaf(B.m00, A.v0, B.v0);
    r.v1  = fmaf(B.m10, A.v0, fmaf(B.m11, A.v1, B.v1));
    return r;
}

__device__ __forceinline__ float2 aff_apply(const Aff& A, float2 s) {
    float2 r;
    r.x = fmaf(A.m00, s.x, A.v0);
    r.y = fmaf(A.m10, s.x, fmaf(A.m11, s.y, A.v1));
    return r;
}

__device__ __forceinline__ Aff aff_shfl_up(const Aff& a, int d) {
    Aff r;
    r.m00 = __shfl_up_sync(0xffffffffu, a.m00, d);
    r.m10 = __shfl_up_sync(0xffffffffu, a.m10, d);
    r.m11 = __shfl_up_sync(0xffffffffu, a.m11, d);
    r.v0  = __shfl_up_sync(0xffffffffu, a.v0,  d);
    r.v1  = __shfl_up_sync(0xffffffffu, a.v1,  d);
    return r;
}

__device__ __forceinline__ void get_params(const float* __restrict__ p,
                                           float& c1, float& c2,
                                           float& attack, float& decay, float& gain) {
    attack = fmaxf(p[0], 1e-7f);
    decay  = fmaxf(p[1], 1e-7f);
    c1 = fminf(fmaxf(p[2], 1e-7f), 0.99f);   // lowpass
    c2 = fminf(fmaxf(p[3], 1e-7f), 0.99f);   // highpass
    gain = fmaxf(p[4], 1e-7f);
}

// Repeated squaring of lower-triangular 2x2
__device__ __forceinline__ void mat_sq_k(float& m00, float& m10, float& m11, int k) {
    #pragma unroll 1
    for (int i = 0; i < k; i++) {
        float n00 = m00 * m00;
        float n10 = m10 * (m00 + m11);
        float n11 = m11 * m11;
        m00 = n00; m10 = n10; m11 = n11;
    }
}

// C = A*B (lower-tri; A,B commute in our use, order irrelevant)
__device__ __forceinline__ void mat_mul(float& c00, float& c10, float& c11,
                                        float a00, float a10, float a11,
                                        float b00, float b10, float b11) {
    c00 = a00 * b00;
    c10 = fmaf(a10, b00, a11 * b10);
    c11 = a11 * b11;
}

// ---------------------------------------------------------------------------
// Init: zero status flags (runs every graph replay, before the main kernel)
// ---------------------------------------------------------------------------
__global__ void ng_init(int G) {
    int i = blockIdx.x * blockDim.x + threadIdx.x;
    if (i < G) g_status[i] = 0;
}

// ---------------------------------------------------------------------------
// Fused single-pass: load once, local scan, publish aggregate, warp-parallel
// aggregate-only lookback, seeded replay + envelope, store once.
// ---------------------------------------------------------------------------
__global__ void __launch_bounds__(BLOCK, 4)
ng_fused(const float* __restrict__ params, const float* __restrict__ x,
         float* __restrict__ out, int n) {
    float c1, c2, at, de, g;
    get_params(params, c1, c2, at, de, g);
    const float b1 = 1.0f - c1;

    const int tid  = threadIdx.x;
    const int bid  = blockIdx.x;
    const int lane = tid & 31, wid = tid >> 5;
    const long base = (long)bid * CHUNK + (long)tid * ITEMS;
    const bool full = (base + ITEMS) <= n;

    // ---- load 32 samples ----
    float xv[ITEMS];
    if (full) {
        const float4* xp = (const float4*)(x + base);
        #pragma unroll
        for (int k = 0; k < ITEMS / 4; k++) {
            float4 v = xp[k];
            xv[4*k+0] = v.x; xv[4*k+1] = v.y; xv[4*k+2] = v.z; xv[4*k+3] = v.w;
        }
    } else {
        #pragma unroll
        for (int j = 0; j < ITEMS; j++)
            xv[j] = (base + j < n) ? x[base + j] : 0.0f;
    }

    // ---- local zero-state sweep ----
    float y1 = 0.0f, y2 = 0.0f;
    #pragma unroll
    for (int j = 0; j < ITEMS; j++) {
        float y1n = fmaf(c1, y1, b1 * xv[j]);
        y2 = c2 * (y2 + (y1n - y1));
        y1 = y1n;
    }

    // ---- thread-segment affine + warp inclusive scan ----
    float m00 = c1, m10 = c2 * (c1 - 1.0f), m11 = c2;
    mat_sq_k(m00, m10, m11, 5);            // A^32
    Aff a = {m00, m10, m11, y1, y2};
    #pragma unroll
    for (int d = 1; d < 32; d <<= 1) {
        Aff o = aff_shfl_up(a, d);
        if (lane >= d) a = aff_combine(a, o);
    }

    __shared__ Aff    wtot[BLOCK / 32];
    __shared__ float2 win[BLOCK / 32];
    __shared__ float2 sin_sh;
    if (lane == 31) wtot[wid] = a;
    __syncthreads();

    if (wid == 0) {
        // thread 0: block aggregate -> publish (release)
        if (lane == 0) {
            Aff t = wtot[0];
            #pragma unroll
            for (int w = 1; w < BLOCK / 32; w++) t = aff_combine(wtot[w], t);
            asm volatile("st.global.cg.v2.f32 [%0], {%1, %2};"
                         :: "l"(g_agg + bid), "f"(t.v0), "f"(t.v1) : "memory");
            asm volatile("st.release.gpu.global.b32 [%0], %1;"
                         :: "l"(g_status + bid), "r"(1) : "memory");
        }

        // warp-parallel aggregate-only lookback:
        // s_in = sum_{d=0..bid-1} (A^CHUNK)^d * agg[bid-1-d]
        float s0x = 0.0f, s0y = 0.0f;
        if (bid > 0) {
            // A_C = A^CHUNK
            float a00 = c1, a10 = c2 * (c1 - 1.0f), a11 = c2;
            mat_sq_k(a00, a10, a11, 13);   // A^8192

            // lane matrix M = A_C^lane ; P ends as A_C^32 (iteration step)
            float p00 = a00, p10 = a10, p11 = a11;
            float M00 = 1.0f, M10 = 0.0f, M11 = 1.0f;
            #pragma unroll
            for (int b = 0; b < 5; b++) {
                if ((lane >> b) & 1) {
                    float t00, t10, t11;
                    mat_mul(t00, t10, t11, M00, M10, M11, p00, p10, p11);
                    M00 = t00; M10 = t10; M11 = t11;
                }
                float q00, q10, q11;
                mat_mul(q00, q10, q11, p00, p10, p11, p00, p10, p11);
                p00 = q00; p10 = q10; p11 = q11;
            }

            float r0 = 0.0f, r1 = 0.0f;
            int j = bid - 1 - lane;
            while (__any_sync(0xffffffffu, j >= 0)) {
                if (j >= 0) {
                    unsigned s;
                    do {
                        asm volatile("ld.acquire.gpu.global.b32 %0, [%1];"
                                     : "=r"(s) : "l"(g_status + j) : "memory");
                    } while (s == 0u);
                    float vx, vy;
                    asm volatile("ld.global.cg.v2.f32 {%0, %1}, [%2];"
                                 : "=f"(vx), "=f"(vy) : "l"(g_agg + j) : "memory");
                    r0 = fmaf(M00, vx, r0);
                    r1 = fmaf(M10, vx, fmaf(M11, vy, r1));
                    // M *= A_C^32
                    float t00, t10, t11;
                    mat_mul(t00, t10, t11, M00, M10, M11, p00, p10, p11);
                    M00 = t00; M10 = t10; M11 = t11;
                }
                j -= 32;
            }
            #pragma unroll
            for (int d = 16; d > 0; d >>= 1) {
                r0 += __shfl_xor_sync(0xffffffffu, r0, d);
                r1 += __shfl_xor_sync(0xffffffffu, r1, d);
            }
            s0x = r0; s0y = r1;
        }
        if (lane == 0) sin_sh = make_float2(s0x, s0y);
    }
    __syncthreads();

    // ---- seed per-warp start states from s_in ----
    if (tid == 0) {
        float2 s = sin_sh;
        #pragma unroll
        for (int w = 0; w < BLOCK / 32; w++) { win[w] = s; s = aff_apply(wtot[w], s); }
    }
    __syncthreads();

    Aff sh = aff_shfl_up(a, 1);
    Aff ex;
    if (lane == 0) { ex.m00 = 1.f; ex.m10 = 0.f; ex.m11 = 1.f; ex.v0 = 0.f; ex.v1 = 0.f; }
    else ex = sh;
    float2 s0 = aff_apply(ex, win[wid]);

    // ---- envelope as geometric sequences ----
    const float inv_n1 = 1.0f / (float)(n - 1);
    const float k1 = 1.0f / de;
    const float k2 = 1.0f / at + k1;
    const float t0 = (float)base * inv_n1;
    float e1 = g * __expf(-t0 * k1);
    float e2 = g * __expf(-t0 * k2);
    const float r1c = __expf(-inv_n1 * k1);
    const float r2c = __expf(-inv_n1 * k2);

    // ---- seeded replay + store ----
    y1 = s0.x; y2 = s0.y;
    if (full) {
        float4* op = (float4*)(out + base);
        #pragma unroll
        for (int k = 0; k < ITEMS / 4; k++) {
            float4 o;
            #pragma unroll
            for (int q = 0; q < 4; q++) {
                float xn = xv[4*k + q];
                float y1n = fmaf(c1, y1, b1 * xn);
                y2 = c2 * (y2 + (y1n - y1));
                y1 = y1n;
                float v = y2 * (e1 - e2);
                e1 *= r1c; e2 *= r2c;
                if (q == 0) o.x = v; else if (q == 1) o.y = v;
                else if (q == 2) o.z = v; else o.w = v;
            }
            op[k] = o;
        }
    } else {
        #pragma unroll
        for (int j = 0; j < ITEMS; j++) {
            float y1n = fmaf(c1, y1, b1 * xv[j]);
            y2 = c2 * (y2 + (y1n - y1));
            y1 = y1n;
            float v = y2 * (e1 - e2);
            e1 *= r1c; e2 *= r2c;
            if (base + j < n) out[base + j] = v;
        }
    }
}

// ---------------------------------------------------------------------------
extern "C" void kernel_launch(void* const* d_in, const int* in_sizes, int n_in,
                              void* d_out, int out_size) {
    int i_par = 0, i_noise = 1;
    if (n_in >= 2 && in_sizes[0] > in_sizes[1]) { i_par = 1; i_noise = 0; }
    const float* params = (const float*)d_in[i_par];
    const float* noise  = (const float*)d_in[i_noise];
    float* out = (float*)d_out;
    const int n = in_sizes[i_noise];
    int G = (n + CHUNK - 1) / CHUNK;
    if (G > MAXBLKS) G = MAXBLKS;  // n = 2^22 -> G = 512

    ng_init<<<(G + 255) / 256, 256>>>(G);
    ng_fused<<<G, BLOCK>>>(params, noise, out, n);
}

// round 4
// speedup vs baseline: 1.4755x; 1.4755x over previous
#include <cuda_runtime.h>

#define ITEMS 16
#define BLOCK 256
#define CHUNK (ITEMS * BLOCK)   // 4096 samples per block
#define NWARP (BLOCK / 32)
#define MAXBLKS 65536

__device__ float2 g_agg[MAXBLKS];   // per-block zero-state end state

// Affine map s' = M s + v, M lower-triangular [[m00,0],[m10,m11]]
struct Aff { float m00, m10, m11, v0, v1; };

__device__ __forceinline__ Aff aff_combine(const Aff& B, const Aff& A) {
    Aff r;
    r.m00 = B.m00 * A.m00;
    r.m10 = fmaf(B.m10, A.m00, B.m11 * A.m10);
    r.m11 = B.m11 * A.m11;
    r.v0  = fmaf(B.m00, A.v0, B.v0);
    r.v1  = fmaf(B.m10, A.v0, fmaf(B.m11, A.v1, B.v1));
    return r;
}

__device__ __forceinline__ float2 aff_apply(const Aff& A, float2 s) {
    float2 r;
    r.x = fmaf(A.m00, s.x, A.v0);
    r.y = fmaf(A.m10, s.x, fmaf(A.m11, s.y, A.v1));
    return r;
}

__device__ __forceinline__ Aff aff_shfl_up(const Aff& a, int d) {
    Aff r;
    r.m00 = __shfl_up_sync(0xffffffffu, a.m00, d);
    r.m10 = __shfl_up_sync(0xffffffffu, a.m10, d);
    r.m11 = __shfl_up_sync(0xffffffffu, a.m11, d);
    r.v0  = __shfl_up_sync(0xffffffffu, a.v0,  d);
    r.v1  = __shfl_up_sync(0xffffffffu, a.v1,  d);
    return r;
}

__device__ __forceinline__ void get_params(const float* __restrict__ p,
                                           float& c1, float& c2,
                                           float& attack, float& decay, float& gain) {
    attack = fmaxf(p[0], 1e-7f);
    decay  = fmaxf(p[1], 1e-7f);
    c1 = fminf(fmaxf(p[2], 1e-7f), 0.99f);   // lowpass
    c2 = fminf(fmaxf(p[3], 1e-7f), 0.99f);   // highpass
    gain = fmaxf(p[4], 1e-7f);
}

__device__ __forceinline__ void mat_sq_k(float& m00, float& m10, float& m11, int k) {
    #pragma unroll 1
    for (int i = 0; i < k; i++) {
        float n00 = m00 * m00;
        float n10 = m10 * (m00 + m11);
        float n11 = m11 * m11;
        m00 = n00; m10 = n10; m11 = n11;
    }
}

__device__ __forceinline__ void mat_mul(float& c00, float& c10, float& c11,
                                        float a00, float a10, float a11,
                                        float b00, float b10, float b11) {
    c00 = a00 * b00;
    c10 = fmaf(a10, b00, a11 * b10);
    c11 = a11 * b11;
}

// ---------------------------------------------------------------------------
// Pass 1: per-block zero-initial-state end state (aggregate)
// ---------------------------------------------------------------------------
__global__ void __launch_bounds__(BLOCK)
ng_pass1(const float* __restrict__ params, const float* __restrict__ x, int n) {
    float c1, c2, at, de, g;
    get_params(params, c1, c2, at, de, g);
    const float b1 = 1.0f - c1;

    const int tid = threadIdx.x;
    const long base = (long)blockIdx.x * CHUNK + (long)tid * ITEMS;

    float xv[ITEMS];
    if (base + ITEMS <= n) {
        const float4* xp = (const float4*)(x + base);
        #pragma unroll
        for (int k = 0; k < ITEMS / 4; k++) {
            float4 v = xp[k];
            xv[4*k+0] = v.x; xv[4*k+1] = v.y; xv[4*k+2] = v.z; xv[4*k+3] = v.w;
        }
    } else {
        #pragma unroll
        for (int j = 0; j < ITEMS; j++)
            xv[j] = (base + j < n) ? x[base + j] : 0.0f;
    }

    float y1 = 0.0f, y2 = 0.0f;
    #pragma unroll
    for (int j = 0; j < ITEMS; j++) {
        float y1n = fmaf(c1, y1, b1 * xv[j]);
        y2 = c2 * (y2 + (y1n - y1));
        y1 = y1n;
    }

    float m00 = c1, m10 = c2 * (c1 - 1.0f), m11 = c2;
    mat_sq_k(m00, m10, m11, 4);            // A^16
    Aff a = {m00, m10, m11, y1, y2};

    const int lane = tid & 31, wid = tid >> 5;
    #pragma unroll
    for (int d = 1; d < 32; d <<= 1) {
        Aff o = aff_shfl_up(a, d);
        if (lane >= d) a = aff_combine(a, o);
    }

    __shared__ Aff wtot[NWARP];
    if (lane == 31) wtot[wid] = a;
    __syncthreads();
    if (tid == 0) {
        Aff t = wtot[0];
        #pragma unroll
        for (int w = 1; w < NWARP; w++) t = aff_combine(wtot[w], t);
        g_agg[blockIdx.x] = make_float2(t.v0, t.v1);
    }
}

// ---------------------------------------------------------------------------
// Pass 2 (fused): parallel lookback over published aggregates (no waiting),
// then seeded replay + envelope + store.
// ---------------------------------------------------------------------------
__global__ void __launch_bounds__(BLOCK)
ng_pass3(const float* __restrict__ params, const float* __restrict__ x,
         float* __restrict__ out, int n) {
    float c1, c2, at, de, g;
    get_params(params, c1, c2, at, de, g);
    const float b1 = 1.0f - c1;

    const int tid  = threadIdx.x;
    const int bid  = blockIdx.x;
    const int lane = tid & 31, wid = tid >> 5;
    const long base = (long)bid * CHUNK + (long)tid * ITEMS;
    const bool full = (base + ITEMS) <= n;

    // ---- load samples ----
    float xv[ITEMS];
    if (full) {
        const float4* xp = (const float4*)(x + base);
        #pragma unroll
        for (int k = 0; k < ITEMS / 4; k++) {
            float4 v = xp[k];
            xv[4*k+0] = v.x; xv[4*k+1] = v.y; xv[4*k+2] = v.z; xv[4*k+3] = v.w;
        }
    } else {
        #pragma unroll
        for (int j = 0; j < ITEMS; j++)
            xv[j] = (base + j < n) ? x[base + j] : 0.0f;
    }

    // ---- local zero-state sweep ----
    float y1 = 0.0f, y2 = 0.0f;
    #pragma unroll
    for (int j = 0; j < ITEMS; j++) {
        float y1n = fmaf(c1, y1, b1 * xv[j]);
        y2 = c2 * (y2 + (y1n - y1));
        y1 = y1n;
    }

    // ---- thread affine + warp inclusive scan ----
    float m00 = c1, m10 = c2 * (c1 - 1.0f), m11 = c2;
    mat_sq_k(m00, m10, m11, 4);            // A^16
    Aff a = {m00, m10, m11, y1, y2};
    #pragma unroll
    for (int d = 1; d < 32; d <<= 1) {
        Aff o = aff_shfl_up(a, d);
        if (lane >= d) a = aff_combine(a, o);
    }

    __shared__ Aff    wtot[NWARP];
    __shared__ float2 wred[NWARP];
    __shared__ float2 win[NWARP];
    if (lane == 31) wtot[wid] = a;

    // ---- fully parallel lookback: s_in = sum_{d=0}^{bid-1} A_C^d * agg[bid-1-d]
    // Thread handles d = tid, tid+BLOCK, tid+2*BLOCK, ...  (no polling: pass1 done)
    float r0 = 0.0f, r1 = 0.0f;
    if (bid > 0) {
        // A_C = A^CHUNK (4096) via 12 squarings
        float a00 = c1, a10 = c2 * (c1 - 1.0f), a11 = c2;
        mat_sq_k(a00, a10, a11, 12);

        // M = A_C^tid  (8-bit binary power); S = A_C^BLOCK (= A_C^256)
        float p00 = a00, p10 = a10, p11 = a11;   // A_C^(2^b)
        float M00 = 1.0f, M10 = 0.0f, M11 = 1.0f;
        float S00 = 1.0f, S10 = 0.0f, S11 = 1.0f;
        #pragma unroll
        for (int b = 0; b < 9; b++) {
            if ((tid >> b) & 1) {
                float t00, t10, t11;
                mat_mul(t00, t10, t11, M00, M10, M11, p00, p10, p11);
                M00 = t00; M10 = t10; M11 = t11;
            }
            if (b == 8) { S00 = p00; S10 = p10; S11 = p11; }  // A_C^256
            float q00, q10, q11;
            mat_mul(q00, q10, q11, p00, p10, p11, p00, p10, p11);
            p00 = q00; p10 = q10; p11 = q11;
        }
        // (for BLOCK=256, S = A_C^256 captured at b==8)

        for (int d = tid; d < bid; d += BLOCK) {
            float2 v = __ldg(&g_agg[bid - 1 - d]);
            r0 = fmaf(M00, v.x, r0);
            r1 = fmaf(M10, v.x, fmaf(M11, v.y, r1));
            float t00, t10, t11;
            mat_mul(t00, t10, t11, M00, M10, M11, S00, S10, S11);
            M00 = t00; M10 = t10; M11 = t11;
        }
    }
    // warp reduce
    #pragma unroll
    for (int d = 16; d > 0; d >>= 1) {
        r0 += __shfl_xor_sync(0xffffffffu, r0, d);
        r1 += __shfl_xor_sync(0xffffffffu, r1, d);
    }
    if (lane == 0) wred[wid] = make_float2(r0, r1);
    __syncthreads();

    // ---- thread 0: finish reduction, seed per-warp start states ----
    if (tid == 0) {
        float2 s = make_float2(0.0f, 0.0f);
        #pragma unroll
        for (int w = 0; w < NWARP; w++) { s.x += wred[w].x; s.y += wred[w].y; }
        #pragma unroll
        for (int w = 0; w < NWARP; w++) { win[w] = s; s = aff_apply(wtot[w], s); }
    }
    __syncthreads();

    Aff sh = aff_shfl_up(a, 1);
    Aff ex;
    if (lane == 0) { ex.m00 = 1.f; ex.m10 = 0.f; ex.m11 = 1.f; ex.v0 = 0.f; ex.v1 = 0.f; }
    else ex = sh;
    float2 s0 = aff_apply(ex, win[wid]);

    // ---- envelope as geometric sequences ----
    const float inv_n1 = 1.0f / (float)(n - 1);
    const float k1 = 1.0f / de;
    const float k2 = 1.0f / at + k1;
    const float t0 = (float)base * inv_n1;
    float e1 = g * __expf(-t0 * k1);
    float e2 = g * __expf(-t0 * k2);
    const float r1c = __expf(-inv_n1 * k1);
    const float r2c = __expf(-inv_n1 * k2);

    // ---- seeded replay + store ----
    y1 = s0.x; y2 = s0.y;
    if (full) {
        float4* op = (float4*)(out + base);
        #pragma unroll
        for (int k = 0; k < ITEMS / 4; k++) {
            float4 o;
            #pragma unroll
            for (int q = 0; q < 4; q++) {
                float xn = xv[4*k + q];
                float y1n = fmaf(c1, y1, b1 * xn);
                y2 = c2 * (y2 + (y1n - y1));
                y1 = y1n;
                float v = y2 * (e1 - e2);
                e1 *= r1c; e2 *= r2c;
                if (q == 0) o.x = v; else if (q == 1) o.y = v;
                else if (q == 2) o.z = v; else o.w = v;
            }
            op[k] = o;
        }
    } else {
        #pragma unroll
        for (int j = 0; j < ITEMS; j++) {
            float y1n = fmaf(c1, y1, b1 * xv[j]);
            y2 = c2 * (y2 + (y1n - y1));
            y1 = y1n;
            float v = y2 * (e1 - e2);
            e1 *= r1c; e2 *= r2c;
            if (base + j < n) out[base + j] = v;
        }
    }
}

// ---------------------------------------------------------------------------
extern "C" void kernel_launch(void* const* d_in, const int* in_sizes, int n_in,
                              void* d_out, int out_size) {
    int i_par = 0, i_noise = 1;
    if (n_in >= 2 && in_sizes[0] > in_sizes[1]) { i_par = 1; i_noise = 0; }
    const float* params = (const float*)d_in[i_par];
    const float* noise  = (const float*)d_in[i_noise];
    float* out = (float*)d_out;
    const int n = in_sizes[i_noise];
    int G = (n + CHUNK - 1) / CHUNK;
    if (G > MAXBLKS) G = MAXBLKS;  // n = 2^22 -> G = 1024

    ng_pass1<<<G, BLOCK>>>(params, noise, n);
    ng_pass3<<<G, BLOCK>>>(params, noise, out, n);
}

// round 5
// speedup vs baseline: 1.6615x; 1.1261x over previous
#include <cuda_runtime.h>

#define ITEMS 16
#define BLOCK 256
#define CHUNK (ITEMS * BLOCK)   // 4096 samples per block
#define NWARP (BLOCK / 32)
#define MAXBLKS 4096            // supports n up to 16.7M (problem: 4.19M -> G=1024)

__device__ float2 g_agg[MAXBLKS];            // per-block zero-state end state
__device__ float2 g_thr[MAXBLKS * BLOCK];    // per-thread block-local inclusive end state

// Affine map s' = M s + v, M lower-triangular [[m00,0],[m10,m11]]
struct Aff { float m00, m10, m11, v0, v1; };

__device__ __forceinline__ Aff aff_combine(const Aff& B, const Aff& A) {
    Aff r;
    r.m00 = B.m00 * A.m00;
    r.m10 = fmaf(B.m10, A.m00, B.m11 * A.m10);
    r.m11 = B.m11 * A.m11;
    r.v0  = fmaf(B.m00, A.v0, B.v0);
    r.v1  = fmaf(B.m10, A.v0, fmaf(B.m11, A.v1, B.v1));
    return r;
}

__device__ __forceinline__ float2 aff_apply(const Aff& A, float2 s) {
    float2 r;
    r.x = fmaf(A.m00, s.x, A.v0);
    r.y = fmaf(A.m10, s.x, fmaf(A.m11, s.y, A.v1));
    return r;
}

__device__ __forceinline__ Aff aff_shfl_up(const Aff& a, int d) {
    Aff r;
    r.m00 = __shfl_up_sync(0xffffffffu, a.m00, d);
    r.m10 = __shfl_up_sync(0xffffffffu, a.m10, d);
    r.m11 = __shfl_up_sync(0xffffffffu, a.m11, d);
    r.v0  = __shfl_up_sync(0xffffffffu, a.v0,  d);
    r.v1  = __shfl_up_sync(0xffffffffu, a.v1,  d);
    return r;
}

__device__ __forceinline__ void get_params(const float* __restrict__ p,
                                           float& c1, float& c2,
                                           float& attack, float& decay, float& gain) {
    attack = fmaxf(p[0], 1e-7f);
    decay  = fmaxf(p[1], 1e-7f);
    c1 = fminf(fmaxf(p[2], 1e-7f), 0.99f);   // lowpass
    c2 = fminf(fmaxf(p[3], 1e-7f), 0.99f);   // highpass
    gain = fmaxf(p[4], 1e-7f);
}

__device__ __forceinline__ void mat_sq_k(float& m00, float& m10, float& m11, int k) {
    #pragma unroll 1
    for (int i = 0; i < k; i++) {
        float n00 = m00 * m00;
        float n10 = m10 * (m00 + m11);
        float n11 = m11 * m11;
        m00 = n00; m10 = n10; m11 = n11;
    }
}

__device__ __forceinline__ void mat_mul(float& c00, float& c10, float& c11,
                                        float a00, float a10, float a11,
                                        float b00, float b10, float b11) {
    c00 = a00 * b00;
    c10 = fmaf(a10, b00, a11 * b10);
    c11 = a11 * b11;
}

// ---------------------------------------------------------------------------
// Pass 1: block scan; publish per-thread block-local inclusive states + block
// aggregate.
// ---------------------------------------------------------------------------
__global__ void __launch_bounds__(BLOCK)
ng_pass1(const float* __restrict__ params, const float* __restrict__ x, int n) {
    float c1, c2, at, de, g;
    get_params(params, c1, c2, at, de, g);
    const float b1 = 1.0f - c1;

    const int tid = threadIdx.x;
    const int bid = blockIdx.x;
    const long base = (long)bid * CHUNK + (long)tid * ITEMS;

    float xv[ITEMS];
    if (base + ITEMS <= n) {
        const float4* xp = (const float4*)(x + base);
        #pragma unroll
        for (int k = 0; k < ITEMS / 4; k++) {
            float4 v = xp[k];
            xv[4*k+0] = v.x; xv[4*k+1] = v.y; xv[4*k+2] = v.z; xv[4*k+3] = v.w;
        }
    } else {
        #pragma unroll
        for (int j = 0; j < ITEMS; j++)
            xv[j] = (base + j < n) ? x[base + j] : 0.0f;
    }

    float y1 = 0.0f, y2 = 0.0f;
    #pragma unroll
    for (int j = 0; j < ITEMS; j++) {
        float y1n = fmaf(c1, y1, b1 * xv[j]);
        y2 = c2 * (y2 + (y1n - y1));
        y1 = y1n;
    }

    float m00 = c1, m10 = c2 * (c1 - 1.0f), m11 = c2;
    mat_sq_k(m00, m10, m11, 4);            // A^16
    Aff a = {m00, m10, m11, y1, y2};

    const int lane = tid & 31, wid = tid >> 5;
    #pragma unroll
    for (int d = 1; d < 32; d <<= 1) {
        Aff o = aff_shfl_up(a, d);
        if (lane >= d) a = aff_combine(a, o);
    }

    __shared__ Aff    wtot[NWARP];
    __shared__ float2 win[NWARP];
    if (lane == 31) wtot[wid] = a;
    __syncthreads();
    if (tid == 0) {
        float2 s = make_float2(0.0f, 0.0f);
        #pragma unroll
        for (int w = 0; w < NWARP; w++) { win[w] = s; s = aff_apply(wtot[w], s); }
        g_agg[bid] = s;   // block aggregate (zero-state end)
    }
    __syncthreads();

    // per-thread block-local inclusive end state
    float2 incl = aff_apply(a, win[wid]);
    g_thr[bid * BLOCK + tid] = incl;
}

// ---------------------------------------------------------------------------
// Pass 2: closed-form seeding (no scan), lookback over aggregates, replay.
// ---------------------------------------------------------------------------
__global__ void __launch_bounds__(BLOCK)
ng_pass3(const float* __restrict__ params, const float* __restrict__ x,
         float* __restrict__ out, int n) {
    float c1, c2, at, de, g;
    get_params(params, c1, c2, at, de, g);
    const float b1 = 1.0f - c1;

    const int tid  = threadIdx.x;
    const int bid  = blockIdx.x;
    const int lane = tid & 31, wid = tid >> 5;
    const long base = (long)bid * CHUNK + (long)tid * ITEMS;
    const bool full = (base + ITEMS) <= n;

    // ---- issue sample loads early (overlap with powering) ----
    float xv[ITEMS];
    if (full) {
        const float4* xp = (const float4*)(x + base);
        #pragma unroll
        for (int k = 0; k < ITEMS / 4; k++) {
            float4 v = xp[k];
            xv[4*k+0] = v.x; xv[4*k+1] = v.y; xv[4*k+2] = v.z; xv[4*k+3] = v.w;
        }
    } else {
        #pragma unroll
        for (int j = 0; j < ITEMS; j++)
            xv[j] = (base + j < n) ? x[base + j] : 0.0f;
    }

    // ---- previous thread's inclusive state (block-local) ----
    float2 vp = make_float2(0.0f, 0.0f);
    if (tid > 0) vp = __ldg(&g_thr[bid * BLOCK + tid - 1]);

    // ---- shared binary-powering chain over A16 ----
    // Mseed = A16^tid  (bits 0..7 of tid)
    // Mlb   = (A16^256)^tid = A_C^tid  (same bits, positions 8..15)
    // S     = A_C^256
    float p00 = c1, p10 = c2 * (c1 - 1.0f), p11 = c2;
    mat_sq_k(p00, p10, p11, 4);                       // A^16
    float Ms00 = 1.0f, Ms10 = 0.0f, Ms11 = 1.0f;
    #pragma unroll
    for (int b = 0; b < 8; b++) {
        if ((tid >> b) & 1) {
            float t00, t10, t11;
            mat_mul(t00, t10, t11, Ms00, Ms10, Ms11, p00, p10, p11);
            Ms00 = t00; Ms10 = t10; Ms11 = t11;
        }
        float q00, q10, q11;
        mat_mul(q00, q10, q11, p00, p10, p11, p00, p10, p11);
        p00 = q00; p10 = q10; p11 = q11;
    }
    // now p = A16^256 = A_C
    float Ml00 = 1.0f, Ml10 = 0.0f, Ml11 = 1.0f;
    #pragma unroll
    for (int b = 0; b < 8; b++) {
        if ((tid >> b) & 1) {
            float t00, t10, t11;
            mat_mul(t00, t10, t11, Ml00, Ml10, Ml11, p00, p10, p11);
            Ml00 = t00; Ml10 = t10; Ml11 = t11;
        }
        float q00, q10, q11;
        mat_mul(q00, q10, q11, p00, p10, p11, p00, p10, p11);
        p00 = q00; p10 = q10; p11 = q11;
    }
    // now p = A_C^256 = S

    // ---- parallel lookback: s_in = sum_{d=0}^{bid-1} A_C^d * agg[bid-1-d] ----
    float r0 = 0.0f, r1 = 0.0f;
    for (int d = tid; d < bid; d += BLOCK) {
        float2 v = __ldg(&g_agg[bid - 1 - d]);
        r0 = fmaf(Ml00, v.x, r0);
        r1 = fmaf(Ml10, v.x, fmaf(Ml11, v.y, r1));
        float t00, t10, t11;
        mat_mul(t00, t10, t11, Ml00, Ml10, Ml11, p00, p10, p11);
        Ml00 = t00; Ml10 = t10; Ml11 = t11;
    }
    #pragma unroll
    for (int d = 16; d > 0; d >>= 1) {
        r0 += __shfl_xor_sync(0xffffffffu, r0, d);
        r1 += __shfl_xor_sync(0xffffffffu, r1, d);
    }
    __shared__ float2 wred[NWARP];
    if (lane == 0) wred[wid] = make_float2(r0, r1);
    __syncthreads();
    float sinx = 0.0f, siny = 0.0f;
    #pragma unroll
    for (int w = 0; w < NWARP; w++) { sinx += wred[w].x; siny += wred[w].y; }

    // ---- closed-form thread seed: s0 = Mseed * s_in + vp ----
    float y1 = fmaf(Ms00, sinx, vp.x);
    float y2 = fmaf(Ms10, sinx, fmaf(Ms11, siny, vp.y));

    // ---- envelope as geometric sequences ----
    const float inv_n1 = 1.0f / (float)(n - 1);
    const float k1 = 1.0f / de;
    const float k2 = 1.0f / at + k1;
    const float t0 = (float)base * inv_n1;
    float e1 = g * __expf(-t0 * k1);
    float e2 = g * __expf(-t0 * k2);
    const float r1c = __expf(-inv_n1 * k1);
    const float r2c = __expf(-inv_n1 * k2);

    // ---- seeded replay + store ----
    if (full) {
        float4* op = (float4*)(out + base);
        #pragma unroll
        for (int k = 0; k < ITEMS / 4; k++) {
            float4 o;
            #pragma unroll
            for (int q = 0; q < 4; q++) {
                float xn = xv[4*k + q];
                float y1n = fmaf(c1, y1, b1 * xn);
                y2 = c2 * (y2 + (y1n - y1));
                y1 = y1n;
                float v = y2 * (e1 - e2);
                e1 *= r1c; e2 *= r2c;
                if (q == 0) o.x = v; else if (q == 1) o.y = v;
                else if (q == 2) o.z = v; else o.w = v;
            }
            op[k] = o;
        }
    } else {
        #pragma unroll
        for (int j = 0; j < ITEMS; j++) {
            float y1n = fmaf(c1, y1, b1 * xv[j]);
            y2 = c2 * (y2 + (y1n - y1));
            y1 = y1n;
            float v = y2 * (e1 - e2);
            e1 *= r1c; e2 *= r2c;
            if (base + j < n) out[base + j] = v;
        }
    }
}

// ---------------------------------------------------------------------------
extern "C" void kernel_launch(void* const* d_in, const int* in_sizes, int n_in,
                              void* d_out, int out_size) {
    int i_par = 0, i_noise = 1;
    if (n_in >= 2 && in_sizes[0] > in_sizes[1]) { i_par = 1; i_noise = 0; }
    const float* params = (const float*)d_in[i_par];
    const float* noise  = (const float*)d_in[i_noise];
    float* out = (float*)d_out;
    const int n = in_sizes[i_noise];
    int G = (n + CHUNK - 1) / CHUNK;
    if (G > MAXBLKS) G = MAXBLKS;  // n = 2^22 -> G = 1024

    ng_pass1<<<G, BLOCK>>>(params, noise, n);
    ng_pass3<<<G, BLOCK>>>(params, noise, out, n);
}

// round 6
// speedup vs baseline: 1.8220x; 1.0966x over previous
#include <cuda_runtime.h>

#define ITEMS 28
#define BLOCK 256
#define CHUNK (ITEMS * BLOCK)   // 7168 samples per block -> G=586 (one wave @4 CTA/SM)
#define NWARP (BLOCK / 32)
#define MAXBLKS 4096

__device__ float2 g_agg[MAXBLKS];            // per-block zero-state end state
__device__ float2 g_thr[MAXBLKS * BLOCK];    // per-thread block-local inclusive end state

// Affine map s' = M s + v, M lower-triangular [[m00,0],[m10,m11]]
struct Aff { float m00, m10, m11, v0, v1; };

__device__ __forceinline__ Aff aff_combine(const Aff& B, const Aff& A) {
    Aff r;
    r.m00 = B.m00 * A.m00;
    r.m10 = fmaf(B.m10, A.m00, B.m11 * A.m10);
    r.m11 = B.m11 * A.m11;
    r.v0  = fmaf(B.m00, A.v0, B.v0);
    r.v1  = fmaf(B.m10, A.v0, fmaf(B.m11, A.v1, B.v1));
    return r;
}

__device__ __forceinline__ float2 aff_apply(const Aff& A, float2 s) {
    float2 r;
    r.x = fmaf(A.m00, s.x, A.v0);
    r.y = fmaf(A.m10, s.x, fmaf(A.m11, s.y, A.v1));
    return r;
}

__device__ __forceinline__ Aff aff_shfl_up(const Aff& a, int d) {
    Aff r;
    r.m00 = __shfl_up_sync(0xffffffffu, a.m00, d);
    r.m10 = __shfl_up_sync(0xffffffffu, a.m10, d);
    r.m11 = __shfl_up_sync(0xffffffffu, a.m11, d);
    r.v0  = __shfl_up_sync(0xffffffffu, a.v0,  d);
    r.v1  = __shfl_up_sync(0xffffffffu, a.v1,  d);
    return r;
}

__device__ __forceinline__ void get_params(const float* __restrict__ p,
                                           float& c1, float& c2,
                                           float& attack, float& decay, float& gain) {
    attack = fmaxf(p[0], 1e-7f);
    decay  = fmaxf(p[1], 1e-7f);
    c1 = fminf(fmaxf(p[2], 1e-7f), 0.99f);   // lowpass
    c2 = fminf(fmaxf(p[3], 1e-7f), 0.99f);   // highpass
    gain = fmaxf(p[4], 1e-7f);
}

__device__ __forceinline__ void mat_mul(float& c00, float& c10, float& c11,
                                        float a00, float a10, float a11,
                                        float b00, float b10, float b11) {
    c00 = a00 * b00;
    c10 = fmaf(a10, b00, a11 * b10);
    c11 = a11 * b11;
}

// M = A^e (e compile-time small), via binary power on lower-tri 2x2
__device__ __forceinline__ void mat_pow_const(float a00, float a10, float a11, int e,
                                              float& M00, float& M10, float& M11) {
    M00 = 1.0f; M10 = 0.0f; M11 = 1.0f;
    float p00 = a00, p10 = a10, p11 = a11;
    #pragma unroll
    for (int b = 0; b < 5; b++) {
        if ((e >> b) & 1) {
            float t00, t10, t11;
            mat_mul(t00, t10, t11, M00, M10, M11, p00, p10, p11);
            M00 = t00; M10 = t10; M11 = t11;
        }
        float q00, q10, q11;
        mat_mul(q00, q10, q11, p00, p10, p11, p00, p10, p11);
        p00 = q00; p10 = q10; p11 = q11;
    }
}

// ---------------------------------------------------------------------------
// Pass 1: block scan; publish per-thread block-local inclusive states + agg.
// ---------------------------------------------------------------------------
__global__ void __launch_bounds__(BLOCK, 4)
ng_pass1(const float* __restrict__ params, const float* __restrict__ x, int n) {
    float c1, c2, at, de, g;
    get_params(params, c1, c2, at, de, g);
    const float b1 = 1.0f - c1;

    const int tid = threadIdx.x;
    const int bid = blockIdx.x;
    const long base = (long)bid * CHUNK + (long)tid * ITEMS;

    float xv[ITEMS];
    if (base + ITEMS <= n) {
        const float4* xp = (const float4*)(x + base);
        #pragma unroll
        for (int k = 0; k < ITEMS / 4; k++) {
            float4 v = xp[k];
            xv[4*k+0] = v.x; xv[4*k+1] = v.y; xv[4*k+2] = v.z; xv[4*k+3] = v.w;
        }
    } else {
        #pragma unroll
        for (int j = 0; j < ITEMS; j++)
            xv[j] = (base + j < n) ? x[base + j] : 0.0f;
    }

    float y1 = 0.0f, y2 = 0.0f;
    #pragma unroll
    for (int j = 0; j < ITEMS; j++) {
        float y1n = fmaf(c1, y1, b1 * xv[j]);
        y2 = c2 * (y2 + (y1n - y1));
        y1 = y1n;
    }

    float a00 = c1, a10 = c2 * (c1 - 1.0f), a11 = c2;
    float m00, m10, m11;
    mat_pow_const(a00, a10, a11, ITEMS, m00, m10, m11);   // A^28
    Aff a = {m00, m10, m11, y1, y2};

    const int lane = tid & 31, wid = tid >> 5;
    #pragma unroll
    for (int d = 1; d < 32; d <<= 1) {
        Aff o = aff_shfl_up(a, d);
        if (lane >= d) a = aff_combine(a, o);
    }

    __shared__ Aff    wtot[NWARP];
    __shared__ float2 win[NWARP];
    if (lane == 31) wtot[wid] = a;
    __syncthreads();
    if (tid == 0) {
        float2 s = make_float2(0.0f, 0.0f);
        #pragma unroll
        for (int w = 0; w < NWARP; w++) { win[w] = s; s = aff_apply(wtot[w], s); }
        g_agg[bid] = s;
    }
    __syncthreads();

    float2 incl = aff_apply(a, win[wid]);
    g_thr[bid * BLOCK + tid] = incl;
}

// ---------------------------------------------------------------------------
// Pass 2: closed-form seeding + parallel lookback + replay + envelope.
// ---------------------------------------------------------------------------
__global__ void __launch_bounds__(BLOCK, 4)
ng_pass3(const float* __restrict__ params, const float* __restrict__ x,
         float* __restrict__ out, int n) {
    float c1, c2, at, de, g;
    get_params(params, c1, c2, at, de, g);
    const float b1 = 1.0f - c1;

    const int tid  = threadIdx.x;
    const int bid  = blockIdx.x;
    const int lane = tid & 31, wid = tid >> 5;
    const long base = (long)bid * CHUNK + (long)tid * ITEMS;
    const bool full = (base + ITEMS) <= n;

    // ---- issue sample loads early ----
    float xv[ITEMS];
    if (full) {
        const float4* xp = (const float4*)(x + base);
        #pragma unroll
        for (int k = 0; k < ITEMS / 4; k++) {
            float4 v = xp[k];
            xv[4*k+0] = v.x; xv[4*k+1] = v.y; xv[4*k+2] = v.z; xv[4*k+3] = v.w;
        }
    } else {
        #pragma unroll
        for (int j = 0; j < ITEMS; j++)
            xv[j] = (base + j < n) ? x[base + j] : 0.0f;
    }

    // ---- previous thread's block-local inclusive state ----
    float2 vp = make_float2(0.0f, 0.0f);
    if (tid > 0) vp = __ldg(&g_thr[bid * BLOCK + tid - 1]);

    // ---- shared binary-powering chain over A28 ----
    float a00 = c1, a10 = c2 * (c1 - 1.0f), a11 = c2;
    float p00, p10, p11;
    mat_pow_const(a00, a10, a11, ITEMS, p00, p10, p11);   // A^28

    // Mseed = A28^tid (bits 0..7), then p -> A28^256 = A_C
    float Ms00 = 1.0f, Ms10 = 0.0f, Ms11 = 1.0f;
    #pragma unroll
    for (int b = 0; b < 8; b++) {
        if ((tid >> b) & 1) {
            float t00, t10, t11;
            mat_mul(t00, t10, t11, Ms00, Ms10, Ms11, p00, p10, p11);
            Ms00 = t00; Ms10 = t10; Ms11 = t11;
        }
        float q00, q10, q11;
        mat_mul(q00, q10, q11, p00, p10, p11, p00, p10, p11);
        p00 = q00; p10 = q10; p11 = q11;
    }
    // Ml = A_C^tid (bits 0..7), then p -> A_C^256
    float Ml00 = 1.0f, Ml10 = 0.0f, Ml11 = 1.0f;
    #pragma unroll
    for (int b = 0; b < 8; b++) {
        if ((tid >> b) & 1) {
            float t00, t10, t11;
            mat_mul(t00, t10, t11, Ml00, Ml10, Ml11, p00, p10, p11);
            Ml00 = t00; Ml10 = t10; Ml11 = t11;
        }
        float q00, q10, q11;
        mat_mul(q00, q10, q11, p00, p10, p11, p00, p10, p11);
        p00 = q00; p10 = q10; p11 = q11;
    }

    // ---- parallel lookback: s_in = sum_{d=0}^{bid-1} A_C^d * agg[bid-1-d] ----
    float r0 = 0.0f, r1 = 0.0f;
    for (int d = tid; d < bid; d += BLOCK) {
        float2 v = __ldg(&g_agg[bid - 1 - d]);
        r0 = fmaf(Ml00, v.x, r0);
        r1 = fmaf(Ml10, v.x, fmaf(Ml11, v.y, r1));
        float t00, t10, t11;
        mat_mul(t00, t10, t11, Ml00, Ml10, Ml11, p00, p10, p11);
        Ml00 = t00; Ml10 = t10; Ml11 = t11;
    }
    #pragma unroll
    for (int d = 16; d > 0; d >>= 1) {
        r0 += __shfl_xor_sync(0xffffffffu, r0, d);
        r1 += __shfl_xor_sync(0xffffffffu, r1, d);
    }
    __shared__ float2 wred[NWARP];
    if (lane == 0) wred[wid] = make_float2(r0, r1);
    __syncthreads();
    float sinx = 0.0f, siny = 0.0f;
    #pragma unroll
    for (int w = 0; w < NWARP; w++) { sinx += wred[w].x; siny += wred[w].y; }

    // ---- closed-form thread seed ----
    float y1 = fmaf(Ms00, sinx, vp.x);
    float y2 = fmaf(Ms10, sinx, fmaf(Ms11, siny, vp.y));

    // ---- envelope as geometric sequences ----
    const float inv_n1 = 1.0f / (float)(n - 1);
    const float k1 = 1.0f / de;
    const float k2 = 1.0f / at + k1;
    const float t0 = (float)base * inv_n1;
    float e1 = g * __expf(-t0 * k1);
    float e2 = g * __expf(-t0 * k2);
    const float r1c = __expf(-inv_n1 * k1);
    const float r2c = __expf(-inv_n1 * k2);

    // ---- seeded replay + store ----
    if (full) {
        float4* op = (float4*)(out + base);
        #pragma unroll
        for (int k = 0; k < ITEMS / 4; k++) {
            float4 o;
            #pragma unroll
            for (int q = 0; q < 4; q++) {
                float xn = xv[4*k + q];
                float y1n = fmaf(c1, y1, b1 * xn);
                y2 = c2 * (y2 + (y1n - y1));
                y1 = y1n;
                float v = y2 * (e1 - e2);
                e1 *= r1c; e2 *= r2c;
                if (q == 0) o.x = v; else if (q == 1) o.y = v;
                else if (q == 2) o.z = v; else o.w = v;
            }
            op[k] = o;
        }
    } else {
        #pragma unroll
        for (int j = 0; j < ITEMS; j++) {
            float y1n = fmaf(c1, y1, b1 * xv[j]);
            y2 = c2 * (y2 + (y1n - y1));
            y1 = y1n;
            float v = y2 * (e1 - e2);
            e1 *= r1c; e2 *= r2c;
            if (base + j < n) out[base + j] = v;
        }
    }
}

// ---------------------------------------------------------------------------
extern "C" void kernel_launch(void* const* d_in, const int* in_sizes, int n_in,
                              void* d_out, int out_size) {
    int i_par = 0, i_noise = 1;
    if (n_in >= 2 && in_sizes[0] > in_sizes[1]) { i_par = 1; i_noise = 0; }
    const float* params = (const float*)d_in[i_par];
    const float* noise  = (const float*)d_in[i_noise];
    float* out = (float*)d_out;
    const int n = in_sizes[i_noise];
    int G = (n + CHUNK - 1) / CHUNK;
    if (G > MAXBLKS) G = MAXBLKS;  // n = 2^22 -> G = 586 (single wave @ 4 CTAs/SM)

    ng_pass1<<<G, BLOCK>>>(params, noise, n);
    ng_pass3<<<G, BLOCK>>>(params, noise, out, n);
}